// round 2
// baseline (speedup 1.0000x reference)
#include <cuda_runtime.h>
#include <math.h>

#define NN 100000
#define NE 1600000
#define DF 64
#define NTILES (NN / 16)
#define WS 66   // padded W row stride (floats): conflict-free float2 LDS

// ---------------- device scratch (static: no allocation allowed) ----------------
__device__ float g_U [NN * DF];
__device__ float g_Vf[NN * DF];
__device__ float g_Vt[NN * DF];
__device__ float g_outinv[NN];
__device__ float g_ininv [NN];
__device__ int   g_degout[NN];
__device__ int   g_degin [NN];
__device__ int   g_rs_fwd[NN + 1];
__device__ int   g_rs_rev[NN + 1];
__device__ int   g_cur_fwd[NN];
__device__ int   g_cur_rev[NN];
__device__ int   g_csr_fwd[NE];   // neighbor (col) indices grouped by row
__device__ int   g_csr_rev[NE];   // neighbor (row) indices grouped by col
__device__ float g_Wr[DF * DF];
__device__ float g_Wi[DF * DF];
__device__ float g_breal[DF];
__device__ float g_bimag[DF];

// ---------------- helpers ----------------
__device__ __forceinline__ void ffma2(unsigned long long& acc,
                                      unsigned long long a,
                                      unsigned long long b) {
    asm("fma.rn.f32x2 %0, %1, %2, %0;" : "+l"(acc) : "l"(a), "l"(b));
}

__device__ __forceinline__ float2 unpack2(unsigned long long v) {
    float2 r;
    asm("mov.b64 {%0, %1}, %2;" : "=f"(r.x), "=f"(r.y) : "l"(v));
    return r;
}

// ---------------- kernels ----------------
// (0) zero degree counters + build effective weights/biases (independent work fused)
__global__ void k_zero_weights(const float* __restrict__ Wr, const float* __restrict__ br,
                               const float* __restrict__ Wi, const float* __restrict__ bi) {
    int i = blockIdx.x * blockDim.x + threadIdx.x;
    if (i < NN) { g_degout[i] = 0; g_degin[i] = 0; }
    if (i < DF * DF) {
        g_Wr[i] = Wr[i] + 0.5f * Wr[4096 + i] + 0.25f * Wr[8192 + i];
        g_Wi[i] = Wi[i] + 0.5f * Wi[4096 + i] + 0.25f * Wi[8192 + i];
    }
    if (i < DF) {
        float bre = br[i] + 0.5f * br[64 + i] + 0.25f * br[128 + i];
        float bie = bi[i] + 0.5f * bi[64 + i] + 0.25f * bi[128 + i];
        g_breal[i] = bre - bie;
        g_bimag[i] = bre + bie;
    }
}

// (1) degree counting
__global__ void k_deg(const int* __restrict__ ei) {
    int i = blockIdx.x * blockDim.x + threadIdx.x;
    if (i < NE) {
        atomicAdd(&g_degout[ei[i]], 1);
        atomicAdd(&g_degin [ei[NE + i]], 1);
    }
}

// (2) deg^-0.25 normalizers
__global__ void k_inv() {
    int i = blockIdx.x * blockDim.x + threadIdx.x;
    if (i < NN) {
        int dout = g_degout[i];
        int din  = g_degin[i];
        g_outinv[i] = (dout > 0) ? powf((float)dout, -0.25f) : 0.0f;
        g_ininv [i] = (din  > 0) ? powf((float)din,  -0.25f) : 0.0f;
    }
}

// (3) single-block exclusive prefix scan over both degree arrays -> CSR offsets + cursors
__global__ __launch_bounds__(1024) void k_scan() {
    __shared__ int sm[1024];
    const int CH = (NN + 1023) / 1024;  // 98
    int t = threadIdx.x;
    for (int p = 0; p < 2; p++) {
        const int* deg = p ? g_degin : g_degout;
        int* rs  = p ? g_rs_rev  : g_rs_fwd;
        int* cur = p ? g_cur_rev : g_cur_fwd;
        int lo = t * CH, hi = min(lo + CH, NN);
        int s = 0;
        for (int i = lo; i < hi; i++) s += deg[i];
        sm[t] = s;
        __syncthreads();
        for (int off = 1; off < 1024; off <<= 1) {
            int v = sm[t];
            int add = (t >= off) ? sm[t - off] : 0;
            __syncthreads();
            sm[t] = v + add;
            __syncthreads();
        }
        int excl = (t == 0) ? 0 : sm[t - 1];
        for (int i = lo; i < hi; i++) {
            rs[i] = excl; cur[i] = excl;
            excl += deg[i];
        }
        if (t == 1023) rs[NN] = NE;
        __syncthreads();
    }
}

// (4) CSR placement: index-only entries (weight reconstructed at gather time)
__global__ void k_place(const int* __restrict__ ei) {
    int e = blockIdx.x * blockDim.x + threadIdx.x;
    if (e < NE) {
        int row = ei[e];
        int col = ei[NE + e];
        int p = atomicAdd(&g_cur_fwd[row], 1);
        g_csr_fwd[p] = col;
        int q = atomicAdd(&g_cur_rev[col], 1);
        g_csr_rev[q] = row;
    }
}

// (5) Fused dense transform:
//   a = xr@Wr, b = xi@Wi, q = xi@Wr, r = xr@Wi
//   U = 0.5(a-b), Vt = 0.5q, Vf = r + 0.5q
__global__ __launch_bounds__(256) void k_transform(const float* __restrict__ xr,
                                                   const float* __restrict__ xi) {
    __shared__ __align__(16) float sWr[DF * WS];
    __shared__ __align__(16) float sWi[DF * WS];
    __shared__ __align__(16) float sx[16 * 2 * DF];

    int t = threadIdx.x;
    for (int i = t; i < DF * DF; i += 256) {
        int o = i >> 6, d = i & 63;
        sWr[o * WS + d] = g_Wr[i];
        sWi[o * WS + d] = g_Wi[i];
    }
    __syncthreads();

    int node = t >> 4;
    int oq   = t & 15;

    for (int tile = blockIdx.x; tile < NTILES; tile += gridDim.x) {
        int nbase = tile * 16;
        for (int i = t; i < 512; i += 256) {
            int nd = i >> 5;
            int k  = i & 31;
            float4 v = (k < 16) ? ((const float4*)xr)[(size_t)(nbase + nd) * 16 + k]
                                : ((const float4*)xi)[(size_t)(nbase + nd) * 16 + (k - 16)];
            ((float4*)sx)[nd * 32 + k] = v;
        }
        __syncthreads();

        unsigned long long accA[4] = {0,0,0,0}, accB[4] = {0,0,0,0};
        unsigned long long accQ[4] = {0,0,0,0}, accR[4] = {0,0,0,0};
        const unsigned long long* xrp = (const unsigned long long*)(sx + node * 128);
        const unsigned long long* xip = (const unsigned long long*)(sx + node * 128 + 64);

        #pragma unroll 8
        for (int d2 = 0; d2 < 32; d2++) {
            unsigned long long x_r = xrp[d2];
            unsigned long long x_i = xip[d2];
            #pragma unroll
            for (int j = 0; j < 4; j++) {
                int o = oq + j * 16;
                unsigned long long wr = *(const unsigned long long*)(sWr + o * WS + 2 * d2);
                unsigned long long wi = *(const unsigned long long*)(sWi + o * WS + 2 * d2);
                ffma2(accA[j], x_r, wr);
                ffma2(accB[j], x_i, wi);
                ffma2(accQ[j], x_i, wr);
                ffma2(accR[j], x_r, wi);
            }
        }

        #pragma unroll
        for (int j = 0; j < 4; j++) {
            float2 fa = unpack2(accA[j]);
            float2 fb = unpack2(accB[j]);
            float2 fq = unpack2(accQ[j]);
            float2 fr = unpack2(accR[j]);
            float a = fa.x + fa.y, b = fb.x + fb.y;
            float q = fq.x + fq.y, r = fr.x + fr.y;
            int o = oq + j * 16;
            size_t gi = (size_t)(nbase + node) * DF + o;
            g_U [gi] = 0.5f * (a - b);
            g_Vt[gi] = 0.5f * q;
            g_Vf[gi] = r + 0.5f * q;
        }
        __syncthreads();
    }
}

// (6) Pull-mode gather: one warp per node, accumulators in registers,
//     zero atomics, bias folded in, single coalesced write per node.
//   out_r[n] = breal + Σ_{e:row=n} w·U[col] + Σ_{e:col=n} w·U[row]
//   out_i[n] = bimag + Σ_{e:row=n} w·Vf[col] + Σ_{e:col=n} w·Vt[row]
//   w = outinv[row]·ininv[col]; one factor constant per node in each pass.
__global__ __launch_bounds__(256) void k_gather(float* __restrict__ out) {
    int n    = (blockIdx.x * 256 + threadIdx.x) >> 5;
    int lane = threadIdx.x & 31;
    if (n >= NN) return;

    float2 accr = ((const float2*)g_breal)[lane];
    float2 acci = ((const float2*)g_bimag)[lane];
    float oinv = g_outinv[n];
    float iinv = g_ininv[n];

    // ---- forward pass: outgoing edges (row == n), gather U/Vf at col ----
    {
        int s = g_rs_fwd[n], e = g_rs_fwd[n + 1];
        for (int base = s; base < e; base += 32) {
            unsigned long long ent = 0;
            if (base + lane < e) {
                int idxl = __ldg(g_csr_fwd + base + lane);
                float w = oinv * __ldg(g_ininv + idxl);
                ent = ((unsigned long long)__float_as_uint(w) << 32) | (unsigned)idxl;
            }
            int m = min(32, e - base);
            for (int j = 0; j < m; j++) {
                unsigned long long v = __shfl_sync(0xffffffffu, ent, j);
                int   idx = (int)(v & 0xffffffffu);
                float w   = __uint_as_float((unsigned)(v >> 32));
                float2 u  = __ldg((const float2*)(g_U  + (size_t)idx * DF) + lane);
                float2 vf = __ldg((const float2*)(g_Vf + (size_t)idx * DF) + lane);
                accr.x = fmaf(w, u.x,  accr.x); accr.y = fmaf(w, u.y,  accr.y);
                acci.x = fmaf(w, vf.x, acci.x); acci.y = fmaf(w, vf.y, acci.y);
            }
        }
    }
    // ---- reverse pass: incoming edges (col == n), gather U/Vt at row ----
    {
        int s = g_rs_rev[n], e = g_rs_rev[n + 1];
        for (int base = s; base < e; base += 32) {
            unsigned long long ent = 0;
            if (base + lane < e) {
                int idxl = __ldg(g_csr_rev + base + lane);
                float w = iinv * __ldg(g_outinv + idxl);
                ent = ((unsigned long long)__float_as_uint(w) << 32) | (unsigned)idxl;
            }
            int m = min(32, e - base);
            for (int j = 0; j < m; j++) {
                unsigned long long v = __shfl_sync(0xffffffffu, ent, j);
                int   idx = (int)(v & 0xffffffffu);
                float w   = __uint_as_float((unsigned)(v >> 32));
                float2 u  = __ldg((const float2*)(g_U  + (size_t)idx * DF) + lane);
                float2 vt = __ldg((const float2*)(g_Vt + (size_t)idx * DF) + lane);
                accr.x = fmaf(w, u.x,  accr.x); accr.y = fmaf(w, u.y,  accr.y);
                acci.x = fmaf(w, vt.x, acci.x); acci.y = fmaf(w, vt.y, acci.y);
            }
        }
    }

    ((float2*)(out + (size_t)n * DF))[lane] = accr;
    ((float2*)(out + (size_t)NN * DF + (size_t)n * DF))[lane] = acci;
}

// ---------------- launch ----------------
extern "C" void kernel_launch(void* const* d_in, const int* in_sizes, int n_in,
                              void* d_out, int out_size) {
    const float* xr = (const float*)d_in[0];
    const float* xi = (const float*)d_in[1];
    const int*   ei = (const int*)  d_in[2];
    const float* Wr = (const float*)d_in[3];
    const float* br = (const float*)d_in[4];
    const float* Wi = (const float*)d_in[5];
    const float* bi = (const float*)d_in[6];
    float* out = (float*)d_out;

    k_zero_weights<<<(NN + 255) / 256, 256>>>(Wr, br, Wi, bi);
    k_deg<<<(NE + 255) / 256, 256>>>(ei);
    k_inv<<<(NN + 255) / 256, 256>>>();
    k_scan<<<1, 1024>>>();
    k_place<<<(NE + 255) / 256, 256>>>(ei);
    k_transform<<<592, 256>>>(xr, xi);
    k_gather<<<(NN * 32 + 255) / 256, 256>>>(out);
}

// round 3
// speedup vs baseline: 1.9396x; 1.9396x over previous
#include <cuda_runtime.h>
#include <math.h>

#define NN 100000
#define NE 1600000
#define DF 64
#define NTILES (NN / 16)
#define WS 66        // padded W row stride (floats): conflict-free float2 LDS
#define SCB 98       // scan blocks: ceil(NN/1024)

// ---------------- device scratch (static: no allocation allowed) ----------------
__device__ float g_U [NN * DF];
__device__ float g_Vf[NN * DF];
__device__ float g_Vt[NN * DF];
__device__ float g_outinv[NN];
__device__ float g_ininv [NN];
__device__ int   g_degout[NN];
__device__ int   g_degin [NN];
__device__ int   g_rs_fwd[NN + 1];
__device__ int   g_rs_rev[NN + 1];
__device__ int   g_cur_fwd[NN];
__device__ int   g_cur_rev[NN];
__device__ int   g_csr_fwd[NE];    // neighbor (col) indices grouped by row
__device__ int   g_csr_rev[NE];    // neighbor (row) indices grouped by col
__device__ int   g_bsum_fwd[SCB];
__device__ int   g_bsum_rev[SCB];
__device__ int   g_bbase_fwd[SCB];
__device__ int   g_bbase_rev[SCB];
__device__ float g_Wr[DF * DF];
__device__ float g_Wi[DF * DF];
__device__ float g_breal[DF];
__device__ float g_bimag[DF];

// ---------------- helpers ----------------
__device__ __forceinline__ void ffma2(unsigned long long& acc,
                                      unsigned long long a,
                                      unsigned long long b) {
    asm("fma.rn.f32x2 %0, %1, %2, %0;" : "+l"(acc) : "l"(a), "l"(b));
}

__device__ __forceinline__ float2 unpack2(unsigned long long v) {
    float2 r;
    asm("mov.b64 {%0, %1}, %2;" : "=f"(r.x), "=f"(r.y) : "l"(v));
    return r;
}

// ---------------- kernels ----------------
// (0) zero degree counters + build effective weights/biases
__global__ void k_zero_weights(const float* __restrict__ Wr, const float* __restrict__ br,
                               const float* __restrict__ Wi, const float* __restrict__ bi) {
    int i = blockIdx.x * blockDim.x + threadIdx.x;
    if (i < NN) { g_degout[i] = 0; g_degin[i] = 0; }
    if (i < DF * DF) {
        g_Wr[i] = Wr[i] + 0.5f * Wr[4096 + i] + 0.25f * Wr[8192 + i];
        g_Wi[i] = Wi[i] + 0.5f * Wi[4096 + i] + 0.25f * Wi[8192 + i];
    }
    if (i < DF) {
        float bre = br[i] + 0.5f * br[64 + i] + 0.25f * br[128 + i];
        float bie = bi[i] + 0.5f * bi[64 + i] + 0.25f * bi[128 + i];
        g_breal[i] = bre - bie;
        g_bimag[i] = bre + bie;
    }
}

// (1) degree counting
__global__ void k_deg(const int* __restrict__ ei) {
    int i = blockIdx.x * blockDim.x + threadIdx.x;
    if (i < NE) {
        atomicAdd(&g_degout[ei[i]], 1);
        atomicAdd(&g_degin [ei[NE + i]], 1);
    }
}

// (2) per-block degree sums (scan stage 1) + deg^-0.25 normalizers (fused)
__global__ __launch_bounds__(1024) void k_bsum_inv() {
    __shared__ int sf[1024], sr[1024];
    int t = threadIdx.x;
    int i = blockIdx.x * 1024 + t;
    int dout = 0, din = 0;
    if (i < NN) {
        dout = g_degout[i];
        din  = g_degin[i];
        g_outinv[i] = (dout > 0) ? rsqrtf(sqrtf((float)dout)) : 0.0f;
        g_ininv [i] = (din  > 0) ? rsqrtf(sqrtf((float)din )) : 0.0f;
    }
    sf[t] = dout; sr[t] = din;
    __syncthreads();
    for (int off = 512; off > 0; off >>= 1) {
        if (t < off) { sf[t] += sf[t + off]; sr[t] += sr[t + off]; }
        __syncthreads();
    }
    if (t == 0) {
        g_bsum_fwd[blockIdx.x] = sf[0];
        g_bsum_rev[blockIdx.x] = sr[0];
    }
}

// (3) scan stage 2: exclusive scan of the 98 block sums (1 small block)
__global__ __launch_bounds__(128) void k_scantop() {
    __shared__ int sf[128], sr[128];
    int t = threadIdx.x;
    sf[t] = (t < SCB) ? g_bsum_fwd[t] : 0;
    sr[t] = (t < SCB) ? g_bsum_rev[t] : 0;
    __syncthreads();
    for (int off = 1; off < 128; off <<= 1) {
        int vf = sf[t], vr = sr[t];
        int af = (t >= off) ? sf[t - off] : 0;
        int ar = (t >= off) ? sr[t - off] : 0;
        __syncthreads();
        sf[t] = vf + af; sr[t] = vr + ar;
        __syncthreads();
    }
    if (t < SCB) {
        g_bbase_fwd[t] = (t == 0) ? 0 : sf[t - 1];
        g_bbase_rev[t] = (t == 0) ? 0 : sr[t - 1];
    }
}

// (4) scan stage 3: in-block exclusive scan + block base -> rs/cur
__global__ __launch_bounds__(1024) void k_offsets() {
    __shared__ int sf[1024], sr[1024];
    int t = threadIdx.x;
    int i = blockIdx.x * 1024 + t;
    int dout = (i < NN) ? g_degout[i] : 0;
    int din  = (i < NN) ? g_degin[i]  : 0;
    sf[t] = dout; sr[t] = din;
    __syncthreads();
    for (int off = 1; off < 1024; off <<= 1) {
        int vf = sf[t], vr = sr[t];
        int af = (t >= off) ? sf[t - off] : 0;
        int ar = (t >= off) ? sr[t - off] : 0;
        __syncthreads();
        sf[t] = vf + af; sr[t] = vr + ar;
        __syncthreads();
    }
    if (i < NN) {
        int of = g_bbase_fwd[blockIdx.x] + sf[t] - dout;  // exclusive
        int orv = g_bbase_rev[blockIdx.x] + sr[t] - din;
        g_rs_fwd[i] = of;  g_cur_fwd[i] = of;
        g_rs_rev[i] = orv; g_cur_rev[i] = orv;
    }
    if (i == NN - 1) { g_rs_fwd[NN] = NE; g_rs_rev[NN] = NE; }
}

// (5) CSR placement: index-only entries
__global__ void k_place(const int* __restrict__ ei) {
    int e = blockIdx.x * blockDim.x + threadIdx.x;
    if (e < NE) {
        int row = ei[e];
        int col = ei[NE + e];
        int p = atomicAdd(&g_cur_fwd[row], 1);
        g_csr_fwd[p] = col;
        int q = atomicAdd(&g_cur_rev[col], 1);
        g_csr_rev[q] = row;
    }
}

// (6) Fused dense transform:
//   a = xr@Wr, b = xi@Wi, q = xi@Wr, r = xr@Wi
//   U = 0.5(a-b), Vt = 0.5q, Vf = r + 0.5q
__global__ __launch_bounds__(256) void k_transform(const float* __restrict__ xr,
                                                   const float* __restrict__ xi) {
    __shared__ __align__(16) float sWr[DF * WS];
    __shared__ __align__(16) float sWi[DF * WS];
    __shared__ __align__(16) float sx[16 * 2 * DF];

    int t = threadIdx.x;
    for (int i = t; i < DF * DF; i += 256) {
        int o = i >> 6, d = i & 63;
        sWr[o * WS + d] = g_Wr[i];
        sWi[o * WS + d] = g_Wi[i];
    }
    __syncthreads();

    int node = t >> 4;
    int oq   = t & 15;

    for (int tile = blockIdx.x; tile < NTILES; tile += gridDim.x) {
        int nbase = tile * 16;
        for (int i = t; i < 512; i += 256) {
            int nd = i >> 5;
            int k  = i & 31;
            float4 v = (k < 16) ? ((const float4*)xr)[(size_t)(nbase + nd) * 16 + k]
                                : ((const float4*)xi)[(size_t)(nbase + nd) * 16 + (k - 16)];
            ((float4*)sx)[nd * 32 + k] = v;
        }
        __syncthreads();

        unsigned long long accA[4] = {0,0,0,0}, accB[4] = {0,0,0,0};
        unsigned long long accQ[4] = {0,0,0,0}, accR[4] = {0,0,0,0};
        const unsigned long long* xrp = (const unsigned long long*)(sx + node * 128);
        const unsigned long long* xip = (const unsigned long long*)(sx + node * 128 + 64);

        #pragma unroll 8
        for (int d2 = 0; d2 < 32; d2++) {
            unsigned long long x_r = xrp[d2];
            unsigned long long x_i = xip[d2];
            #pragma unroll
            for (int j = 0; j < 4; j++) {
                int o = oq + j * 16;
                unsigned long long wr = *(const unsigned long long*)(sWr + o * WS + 2 * d2);
                unsigned long long wi = *(const unsigned long long*)(sWi + o * WS + 2 * d2);
                ffma2(accA[j], x_r, wr);
                ffma2(accB[j], x_i, wi);
                ffma2(accQ[j], x_i, wr);
                ffma2(accR[j], x_r, wi);
            }
        }

        #pragma unroll
        for (int j = 0; j < 4; j++) {
            float2 fa = unpack2(accA[j]);
            float2 fb = unpack2(accB[j]);
            float2 fq = unpack2(accQ[j]);
            float2 fr = unpack2(accR[j]);
            float a = fa.x + fa.y, b = fb.x + fb.y;
            float q = fq.x + fq.y, r = fr.x + fr.y;
            int o = oq + j * 16;
            size_t gi = (size_t)(nbase + node) * DF + o;
            g_U [gi] = 0.5f * (a - b);
            g_Vt[gi] = 0.5f * q;
            g_Vf[gi] = r + 0.5f * q;
        }
        __syncthreads();
    }
}

// (7) Pull-mode gather: one warp per node, accumulators in registers,
//     zero float atomics, bias folded in, single coalesced write per node.
__global__ __launch_bounds__(256) void k_gather(float* __restrict__ out) {
    int n    = (blockIdx.x * 256 + threadIdx.x) >> 5;
    int lane = threadIdx.x & 31;
    if (n >= NN) return;

    float2 accr = ((const float2*)g_breal)[lane];
    float2 acci = ((const float2*)g_bimag)[lane];
    float oinv = g_outinv[n];
    float iinv = g_ininv[n];

    // ---- forward: outgoing edges (row == n), gather U/Vf at col ----
    {
        int s = g_rs_fwd[n], e = g_rs_fwd[n + 1];
        for (int base = s; base < e; base += 32) {
            unsigned long long ent = 0;
            if (base + lane < e) {
                int idxl = __ldg(g_csr_fwd + base + lane);
                float w = oinv * __ldg(g_ininv + idxl);
                ent = ((unsigned long long)__float_as_uint(w) << 32) | (unsigned)idxl;
            }
            int m = min(32, e - base);
            for (int j = 0; j < m; j++) {
                unsigned long long v = __shfl_sync(0xffffffffu, ent, j);
                int   idx = (int)(v & 0xffffffffu);
                float w   = __uint_as_float((unsigned)(v >> 32));
                float2 u  = __ldg((const float2*)(g_U  + (size_t)idx * DF) + lane);
                float2 vf = __ldg((const float2*)(g_Vf + (size_t)idx * DF) + lane);
                accr.x = fmaf(w, u.x,  accr.x); accr.y = fmaf(w, u.y,  accr.y);
                acci.x = fmaf(w, vf.x, acci.x); acci.y = fmaf(w, vf.y, acci.y);
            }
        }
    }
    // ---- reverse: incoming edges (col == n), gather U/Vt at row ----
    {
        int s = g_rs_rev[n], e = g_rs_rev[n + 1];
        for (int base = s; base < e; base += 32) {
            unsigned long long ent = 0;
            if (base + lane < e) {
                int idxl = __ldg(g_csr_rev + base + lane);
                float w = iinv * __ldg(g_outinv + idxl);
                ent = ((unsigned long long)__float_as_uint(w) << 32) | (unsigned)idxl;
            }
            int m = min(32, e - base);
            for (int j = 0; j < m; j++) {
                unsigned long long v = __shfl_sync(0xffffffffu, ent, j);
                int   idx = (int)(v & 0xffffffffu);
                float w   = __uint_as_float((unsigned)(v >> 32));
                float2 u  = __ldg((const float2*)(g_U  + (size_t)idx * DF) + lane);
                float2 vt = __ldg((const float2*)(g_Vt + (size_t)idx * DF) + lane);
                accr.x = fmaf(w, u.x,  accr.x); accr.y = fmaf(w, u.y,  accr.y);
                acci.x = fmaf(w, vt.x, acci.x); acci.y = fmaf(w, vt.y, acci.y);
            }
        }
    }

    ((float2*)(out + (size_t)n * DF))[lane] = accr;
    ((float2*)(out + (size_t)NN * DF + (size_t)n * DF))[lane] = acci;
}

// ---------------- launch ----------------
extern "C" void kernel_launch(void* const* d_in, const int* in_sizes, int n_in,
                              void* d_out, int out_size) {
    const float* xr = (const float*)d_in[0];
    const float* xi = (const float*)d_in[1];
    const int*   ei = (const int*)  d_in[2];
    const float* Wr = (const float*)d_in[3];
    const float* br = (const float*)d_in[4];
    const float* Wi = (const float*)d_in[5];
    const float* bi = (const float*)d_in[6];
    float* out = (float*)d_out;

    k_zero_weights<<<(NN + 255) / 256, 256>>>(Wr, br, Wi, bi);
    k_deg<<<(NE + 255) / 256, 256>>>(ei);
    k_bsum_inv<<<SCB, 1024>>>();
    k_scantop<<<1, 128>>>();
    k_offsets<<<SCB, 1024>>>();
    k_place<<<(NE + 255) / 256, 256>>>(ei);
    k_transform<<<592, 256>>>(xr, xi);
    k_gather<<<(NN * 32 + 255) / 256, 256>>>(out);
}

// round 4
// speedup vs baseline: 2.2459x; 1.1579x over previous
#include <cuda_runtime.h>
#include <cuda_fp16.h>
#include <math.h>

#define NN 100000
#define NE 1600000
#define DF 64
#define NTILES (NN / 16)
#define WS 66        // padded W row stride (floats): conflict-free float2 LDS
#define SCB 98       // scan blocks: ceil(NN/1024)

// ---------------- device scratch (static: no allocation allowed) ----------------
__device__ __half g_UVf[NN * 128];  // per node: U[0:64] then Vf[0:64]  (fp16)
__device__ __half g_UVt[NN * 128];  // per node: U[0:64] then Vt[0:64]  (fp16)
__device__ float g_outinv[NN];
__device__ float g_ininv [NN];
__device__ int   g_degout[NN];
__device__ int   g_degin [NN];
__device__ int   g_rs_fwd[NN + 1];
__device__ int   g_rs_rev[NN + 1];
__device__ int   g_cur_fwd[NN];
__device__ int   g_cur_rev[NN];
__device__ int   g_csr_fwd[NE];    // neighbor (col) indices grouped by row
__device__ int   g_csr_rev[NE];    // neighbor (row) indices grouped by col
__device__ int   g_bsum_fwd[SCB];
__device__ int   g_bsum_rev[SCB];
__device__ int   g_bbase_fwd[SCB];
__device__ int   g_bbase_rev[SCB];
__device__ float g_Wr[DF * DF];
__device__ float g_Wi[DF * DF];
__device__ float g_bias[128];      // [0:64) breal_eff, [64:128) bimag_eff

// ---------------- helpers ----------------
__device__ __forceinline__ void ffma2(unsigned long long& acc,
                                      unsigned long long a,
                                      unsigned long long b) {
    asm("fma.rn.f32x2 %0, %1, %2, %0;" : "+l"(acc) : "l"(a), "l"(b));
}

__device__ __forceinline__ float2 unpack2(unsigned long long v) {
    float2 r;
    asm("mov.b64 {%0, %1}, %2;" : "=f"(r.x), "=f"(r.y) : "l"(v));
    return r;
}

// ---------------- kernels ----------------
// (0) zero degree counters + build effective weights/biases
__global__ void k_zero_weights(const float* __restrict__ Wr, const float* __restrict__ br,
                               const float* __restrict__ Wi, const float* __restrict__ bi) {
    int i = blockIdx.x * blockDim.x + threadIdx.x;
    if (i < NN) { g_degout[i] = 0; g_degin[i] = 0; }
    if (i < DF * DF) {
        g_Wr[i] = Wr[i] + 0.5f * Wr[4096 + i] + 0.25f * Wr[8192 + i];
        g_Wi[i] = Wi[i] + 0.5f * Wi[4096 + i] + 0.25f * Wi[8192 + i];
    }
    if (i < DF) {
        float bre = br[i] + 0.5f * br[64 + i] + 0.25f * br[128 + i];
        float bie = bi[i] + 0.5f * bi[64 + i] + 0.25f * bi[128 + i];
        g_bias[i]      = bre - bie;   // real bias
        g_bias[64 + i] = bre + bie;   // imag bias
    }
}

// (1) degree counting
__global__ void k_deg(const int* __restrict__ ei) {
    int i = blockIdx.x * blockDim.x + threadIdx.x;
    if (i < NE) {
        atomicAdd(&g_degout[ei[i]], 1);
        atomicAdd(&g_degin [ei[NE + i]], 1);
    }
}

// (2) per-block degree sums (scan stage 1) + deg^-0.25 normalizers (fused)
__global__ __launch_bounds__(1024) void k_bsum_inv() {
    __shared__ int sf[1024], sr[1024];
    int t = threadIdx.x;
    int i = blockIdx.x * 1024 + t;
    int dout = 0, din = 0;
    if (i < NN) {
        dout = g_degout[i];
        din  = g_degin[i];
        g_outinv[i] = (dout > 0) ? rsqrtf(sqrtf((float)dout)) : 0.0f;
        g_ininv [i] = (din  > 0) ? rsqrtf(sqrtf((float)din )) : 0.0f;
    }
    sf[t] = dout; sr[t] = din;
    __syncthreads();
    for (int off = 512; off > 0; off >>= 1) {
        if (t < off) { sf[t] += sf[t + off]; sr[t] += sr[t + off]; }
        __syncthreads();
    }
    if (t == 0) {
        g_bsum_fwd[blockIdx.x] = sf[0];
        g_bsum_rev[blockIdx.x] = sr[0];
    }
}

// (3) scan stage 2: exclusive scan of the 98 block sums
__global__ __launch_bounds__(128) void k_scantop() {
    __shared__ int sf[128], sr[128];
    int t = threadIdx.x;
    sf[t] = (t < SCB) ? g_bsum_fwd[t] : 0;
    sr[t] = (t < SCB) ? g_bsum_rev[t] : 0;
    __syncthreads();
    for (int off = 1; off < 128; off <<= 1) {
        int vf = sf[t], vr = sr[t];
        int af = (t >= off) ? sf[t - off] : 0;
        int ar = (t >= off) ? sr[t - off] : 0;
        __syncthreads();
        sf[t] = vf + af; sr[t] = vr + ar;
        __syncthreads();
    }
    if (t < SCB) {
        g_bbase_fwd[t] = (t == 0) ? 0 : sf[t - 1];
        g_bbase_rev[t] = (t == 0) ? 0 : sr[t - 1];
    }
}

// (4) scan stage 3: in-block exclusive scan + block base -> rs/cur
__global__ __launch_bounds__(1024) void k_offsets() {
    __shared__ int sf[1024], sr[1024];
    int t = threadIdx.x;
    int i = blockIdx.x * 1024 + t;
    int dout = (i < NN) ? g_degout[i] : 0;
    int din  = (i < NN) ? g_degin[i]  : 0;
    sf[t] = dout; sr[t] = din;
    __syncthreads();
    for (int off = 1; off < 1024; off <<= 1) {
        int vf = sf[t], vr = sr[t];
        int af = (t >= off) ? sf[t - off] : 0;
        int ar = (t >= off) ? sr[t - off] : 0;
        __syncthreads();
        sf[t] = vf + af; sr[t] = vr + ar;
        __syncthreads();
    }
    if (i < NN) {
        int of  = g_bbase_fwd[blockIdx.x] + sf[t] - dout;  // exclusive
        int orv = g_bbase_rev[blockIdx.x] + sr[t] - din;
        g_rs_fwd[i] = of;  g_cur_fwd[i] = of;
        g_rs_rev[i] = orv; g_cur_rev[i] = orv;
    }
    if (i == NN - 1) { g_rs_fwd[NN] = NE; g_rs_rev[NN] = NE; }
}

// (5) CSR placement
__global__ void k_place(const int* __restrict__ ei) {
    int e = blockIdx.x * blockDim.x + threadIdx.x;
    if (e < NE) {
        int row = ei[e];
        int col = ei[NE + e];
        int p = atomicAdd(&g_cur_fwd[row], 1);
        g_csr_fwd[p] = col;
        int q = atomicAdd(&g_cur_rev[col], 1);
        g_csr_rev[q] = row;
    }
}

// (6) Fused dense transform -> fp16 interleaved node vectors:
//   a = xr@Wr, b = xi@Wi, q = xi@Wr, r = xr@Wi
//   U = 0.5(a-b), Vt = 0.5q, Vf = r + 0.5q
//   UVf[n] = {U, Vf},  UVt[n] = {U, Vt}
__global__ __launch_bounds__(256) void k_transform(const float* __restrict__ xr,
                                                   const float* __restrict__ xi) {
    __shared__ __align__(16) float sWr[DF * WS];
    __shared__ __align__(16) float sWi[DF * WS];
    __shared__ __align__(16) float sx[16 * 2 * DF];

    int t = threadIdx.x;
    for (int i = t; i < DF * DF; i += 256) {
        int o = i >> 6, d = i & 63;
        sWr[o * WS + d] = g_Wr[i];
        sWi[o * WS + d] = g_Wi[i];
    }
    __syncthreads();

    int node = t >> 4;
    int oq   = t & 15;

    for (int tile = blockIdx.x; tile < NTILES; tile += gridDim.x) {
        int nbase = tile * 16;
        for (int i = t; i < 512; i += 256) {
            int nd = i >> 5;
            int k  = i & 31;
            float4 v = (k < 16) ? ((const float4*)xr)[(size_t)(nbase + nd) * 16 + k]
                                : ((const float4*)xi)[(size_t)(nbase + nd) * 16 + (k - 16)];
            ((float4*)sx)[nd * 32 + k] = v;
        }
        __syncthreads();

        unsigned long long accA[4] = {0,0,0,0}, accB[4] = {0,0,0,0};
        unsigned long long accQ[4] = {0,0,0,0}, accR[4] = {0,0,0,0};
        const unsigned long long* xrp = (const unsigned long long*)(sx + node * 128);
        const unsigned long long* xip = (const unsigned long long*)(sx + node * 128 + 64);

        #pragma unroll 8
        for (int d2 = 0; d2 < 32; d2++) {
            unsigned long long x_r = xrp[d2];
            unsigned long long x_i = xip[d2];
            #pragma unroll
            for (int j = 0; j < 4; j++) {
                int o = oq + j * 16;
                unsigned long long wr = *(const unsigned long long*)(sWr + o * WS + 2 * d2);
                unsigned long long wi = *(const unsigned long long*)(sWi + o * WS + 2 * d2);
                ffma2(accA[j], x_r, wr);
                ffma2(accB[j], x_i, wi);
                ffma2(accQ[j], x_i, wr);
                ffma2(accR[j], x_r, wi);
            }
        }

        size_t nb = (size_t)(nbase + node) * 128;
        #pragma unroll
        for (int j = 0; j < 4; j++) {
            float2 fa = unpack2(accA[j]);
            float2 fb = unpack2(accB[j]);
            float2 fq = unpack2(accQ[j]);
            float2 fr = unpack2(accR[j]);
            float a = fa.x + fa.y, b = fb.x + fb.y;
            float q = fq.x + fq.y, r = fr.x + fr.y;
            int o = oq + j * 16;
            __half hU  = __float2half_rn(0.5f * (a - b));
            __half hVf = __float2half_rn(r + 0.5f * q);
            __half hVt = __float2half_rn(0.5f * q);
            g_UVf[nb + o]      = hU;
            g_UVf[nb + 64 + o] = hVf;
            g_UVt[nb + o]      = hU;
            g_UVt[nb + 64 + o] = hVt;
        }
        __syncthreads();
    }
}

// (7) Pull-mode gather: one warp per node. Per edge-visit: ONE warp-wide
//     LDG.64 over a contiguous 256B fp16 block. Lanes 0-15 accumulate the
//     real half (U), lanes 16-31 the imag half (Vf or Vt). Zero atomics.
__global__ __launch_bounds__(256) void k_gather(float* __restrict__ out) {
    int n    = (blockIdx.x * 256 + threadIdx.x) >> 5;
    int lane = threadIdx.x & 31;
    if (n >= NN) return;

    // lane l owns component dims [4l, 4l+4) of the 128-wide {real|imag} vector
    float4 acc = ((const float4*)g_bias)[lane];
    float oinv = g_outinv[n];
    float iinv = g_ininv[n];

    // ---- forward: outgoing edges (row == n), gather UVf[col] ----
    {
        int s = g_rs_fwd[n], e = g_rs_fwd[n + 1];
        for (int base = s; base < e; base += 32) {
            unsigned long long ent = 0;
            if (base + lane < e) {
                int idxl = __ldg(g_csr_fwd + base + lane);
                float w = oinv * __ldg(g_ininv + idxl);
                ent = ((unsigned long long)__float_as_uint(w) << 32) | (unsigned)idxl;
            }
            int m = min(32, e - base);
            for (int j = 0; j < m; j++) {
                unsigned long long v = __shfl_sync(0xffffffffu, ent, j);
                int   idx = (int)(v & 0xffffffffu);
                float w   = __uint_as_float((unsigned)(v >> 32));
                uint2 pk  = __ldg((const uint2*)(g_UVf + (size_t)idx * 128) + lane);
                float2 f0 = __half22float2(*(const __half2*)&pk.x);
                float2 f1 = __half22float2(*(const __half2*)&pk.y);
                acc.x = fmaf(w, f0.x, acc.x); acc.y = fmaf(w, f0.y, acc.y);
                acc.z = fmaf(w, f1.x, acc.z); acc.w = fmaf(w, f1.y, acc.w);
            }
        }
    }
    // ---- reverse: incoming edges (col == n), gather UVt[row] ----
    {
        int s = g_rs_rev[n], e = g_rs_rev[n + 1];
        for (int base = s; base < e; base += 32) {
            unsigned long long ent = 0;
            if (base + lane < e) {
                int idxl = __ldg(g_csr_rev + base + lane);
                float w = iinv * __ldg(g_outinv + idxl);
                ent = ((unsigned long long)__float_as_uint(w) << 32) | (unsigned)idxl;
            }
            int m = min(32, e - base);
            for (int j = 0; j < m; j++) {
                unsigned long long v = __shfl_sync(0xffffffffu, ent, j);
                int   idx = (int)(v & 0xffffffffu);
                float w   = __uint_as_float((unsigned)(v >> 32));
                uint2 pk  = __ldg((const uint2*)(g_UVt + (size_t)idx * 128) + lane);
                float2 f0 = __half22float2(*(const __half2*)&pk.x);
                float2 f1 = __half22float2(*(const __half2*)&pk.y);
                acc.x = fmaf(w, f0.x, acc.x); acc.y = fmaf(w, f0.y, acc.y);
                acc.z = fmaf(w, f1.x, acc.z); acc.w = fmaf(w, f1.y, acc.w);
            }
        }
    }

    // lanes 0-15: real dims 4l..4l+3 ; lanes 16-31: imag dims 4(l-16)..
    if (lane < 16) {
        ((float4*)(out + (size_t)n * DF))[lane] = acc;
    } else {
        ((float4*)(out + (size_t)NN * DF + (size_t)n * DF))[lane - 16] = acc;
    }
}

// ---------------- launch ----------------
extern "C" void kernel_launch(void* const* d_in, const int* in_sizes, int n_in,
                              void* d_out, int out_size) {
    const float* xr = (const float*)d_in[0];
    const float* xi = (const float*)d_in[1];
    const int*   ei = (const int*)  d_in[2];
    const float* Wr = (const float*)d_in[3];
    const float* br = (const float*)d_in[4];
    const float* Wi = (const float*)d_in[5];
    const float* bi = (const float*)d_in[6];
    float* out = (float*)d_out;

    k_zero_weights<<<(NN + 255) / 256, 256>>>(Wr, br, Wi, bi);
    k_deg<<<(NE + 255) / 256, 256>>>(ei);
    k_bsum_inv<<<SCB, 1024>>>();
    k_scantop<<<1, 128>>>();
    k_offsets<<<SCB, 1024>>>();
    k_place<<<(NE + 255) / 256, 256>>>(ei);
    k_transform<<<592, 256>>>(xr, xi);
    k_gather<<<(NN * 32 + 255) / 256, 256>>>(out);
}